// round 14
// baseline (speedup 1.0000x reference)
#include <cuda_runtime.h>

// INRF: out[b,i,j,c] = sum_yx M[ij,yx]*in[b,yx,c]
//                    - L * sum_yx W[ij,yx]*relu(in[b,yx,c] - shifted[b,ij,yx,c])
// shifted[b,ij,y,x,f] = sum_{kh,kw,c} in[b,y+kh-1,x+kw-1,c] * G[ij,kh,kw,c,f]
// B=4, H=W=32, C=F=16, KH=KW=3, L=1, SAME padding.
//
// One CTA per (i,j), 256 threads. F-SPLIT layout: warps 0-3 compute filters
// 0-7, warps 4-7 compute filters 8-15 (independent outputs, no combine).
// Each thread: 8 positions x 4 filter-pairs -> 32 u64 accumulators (64 regs),
// total ~110 regs -> 2 CTAs/SM (16 warps). Per (kk,c) warp-unit:
// L1 = 8wf(g, 2xLDS.128) + 8wf(a) = 16 wf vs fma = 64 cyc -> balanced 1:1
// at the dual floor (~268us), vs R8's 320/256 L1-bound split.

typedef unsigned long long u64;
#define FULLMASK 0xFFFFFFFFu

#define FMA2(d, a, b, c) \
    asm("fma.rn.f32x2 %0, %1, %2, %3;" : "=l"(d) : "l"(a), "l"(b), "l"(c))

__device__ __forceinline__ u64 pk(float x) {
    u64 v = (u64)__float_as_uint(x);
    return v | (v << 32);
}
__device__ __forceinline__ float lo32(u64 v) {
    return __uint_as_float((unsigned)v);
}
__device__ __forceinline__ float hi32(u64 v) {
    return __uint_as_float((unsigned)(v >> 32));
}

// SMEM layout (floats):
//  [0,2304)        G[ij]  : [kh][kw][c][f]
//  [2304,3328)     M row  : 1024
//  [3328,4352)     W row  : 1024
//  [4352,22848)    input tile, channel-major padded: [16][34][34]
//  [22848,23360)   reduction buffer (8 warps x 8 used)
#define OFF_M   2304
#define OFF_W   3328
#define OFF_IN  4352
#define OFF_RED 22848
#define SMEM_FLOATS 23360
#define SMEM_BYTES  (SMEM_FLOATS * 4)
#define IN_T (16 * 34 * 34)   // 18496

__global__ __launch_bounds__(256)
void inrf_kernel(const float* __restrict__ in,   // [4][32][32][16]
                 const float* __restrict__ Mm,   // [1024][1024]
                 const float* __restrict__ Ww,   // [1024][1024]
                 const float* __restrict__ Gg,   // [1024][3][3][16][16]
                 float* __restrict__ out)        // [4][32][32][16]
{
    extern __shared__ float sm[];
    float* sG   = sm;
    float* sM   = sm + OFF_M;
    float* sW   = sm + OFF_W;
    float* sIn  = sm + OFF_IN;
    float* sRed = sm + OFF_RED;

    const int ij = blockIdx.x;       // 0..1023
    const int t  = threadIdx.x;      // 0..255
    const int warp = t >> 5, lane = t & 31;
    const int fh = warp >> 2;        // filter half: 0 -> f0-7, 1 -> f8-15
    const int pw = warp & 3;         // position-warp 0..3
    const int fb = fh << 3;          // filter base (0 or 8)

    // Load per-(i,j) weights
    for (int i = t; i < 2304; i += 256) sG[i] = Gg[ij * 2304 + i];
    for (int i = t; i < 1024; i += 256) {
        sM[i] = Mm[ij * 1024 + i];
        sW[i] = Ww[ij * 1024 + i];
    }

    // This thread's 8 positions: pos_p = pw*32 + lane + p*128
    //   -> y = pw + p*4, x = lane  (rows 4 apart)
    const int y0 = pw;               // 0..3
    const int x0 = lane;             // 0..31

    for (int b = 0; b < 4; b++) {
        __syncthreads();  // protect sIn (and sRed/sG on first iter)
        // Load image b, channel-major, zero-padded: sIn[c*1156 + (y+1)*34 + (x+1)]
        for (int i = t; i < IN_T; i += 256) {
            int c = i / 1156;
            int r = i - c * 1156;
            int y = r / 34 - 1;
            int x = r - (y + 1) * 34 - 1;
            float v = 0.0f;
            if ((unsigned)y < 32u && (unsigned)x < 32u)
                v = in[b * 16384 + y * 512 + x * 16 + c];
            sIn[i] = v;
        }
        __syncthreads();

        // Packed shifted accumulators: 8 positions x 4 filter-pairs (my f-half).
        u64 s[8][4];
        #pragma unroll
        for (int p = 0; p < 8; p++)
            #pragma unroll
            for (int k = 0; k < 4; k++) s[p][k] = 0ull;

        for (int kk = 0; kk < 9; kk++) {
            const int kh = kk / 3, kw = kk - kh * 3;
            const int o = (y0 + kh) * 34 + (x0 + kw);
            // g pairs for my f-half: floats [kk*256 + c*16 + fb .. +8)
            const ulonglong2* gq =
                reinterpret_cast<const ulonglong2*>(sG + (kk << 8) + fb);
            #pragma unroll
            for (int c = 0; c < 16; c++) {
                const float* pc = sIn + c * 1156 + o;
                // Batch the 8 input loads (MLP), then g, then the FMA block.
                float a[8];
                #pragma unroll
                for (int p = 0; p < 8; p++) a[p] = pc[p * 136];  // 4 rows apart
                const ulonglong2 q0 = gq[c << 2];        // 16-float stride = 4 u128
                const ulonglong2 q1 = gq[(c << 2) + 1];
                #pragma unroll
                for (int p = 0; p < 8; p++) {
                    const u64 ap = pk(a[p]);
                    FMA2(s[p][0], ap, q0.x, s[p][0]);
                    FMA2(s[p][1], ap, q0.y, s[p][1]);
                    FMA2(s[p][2], ap, q1.x, s[p][2]);
                    FMA2(s[p][3], ap, q1.y, s[p][3]);
                }
            }
        }

        // Epilogue: acc8[k] = sum_p m_p*iv - w_p*relu(iv - shifted)   (L = 1)
        float acc8[8];
        #pragma unroll
        for (int k = 0; k < 8; k++) acc8[k] = 0.0f;
        #pragma unroll
        for (int p = 0; p < 8; p++) {
            const int yx = pw * 32 + lane + p * 128;
            const float wv = sW[yx], mv = sM[yx];
            const float* iv = sIn + (y0 + p * 4 + 1) * 34 + (x0 + 1);
            #pragma unroll
            for (int k = 0; k < 4; k++) {
                const float v0 = iv[(fb + 2 * k) * 1156];
                const float v1 = iv[(fb + 2 * k + 1) * 1156];
                acc8[2 * k]     += mv * v0 - wv * fmaxf(v0 - lo32(s[p][k]), 0.0f);
                acc8[2 * k + 1] += mv * v1 - wv * fmaxf(v1 - hi32(s[p][k]), 0.0f);
            }
        }

        // Reduce acc8 over the 32 lanes of each warp, then over the 4
        // position-warps of each f-half.
        #pragma unroll
        for (int k = 0; k < 8; k++) {
            #pragma unroll
            for (int off = 16; off; off >>= 1)
                acc8[k] += __shfl_down_sync(FULLMASK, acc8[k], off);
        }
        if (lane == 0) {
            #pragma unroll
            for (int k = 0; k < 8; k++) sRed[warp * 8 + k] = acc8[k];
        }
        __syncthreads();
        if (t < 16) {
            const int f = t;
            const int fh2 = f >> 3, kf = f & 7;
            float sv = 0.0f;
            #pragma unroll
            for (int w4 = 0; w4 < 4; w4++)
                sv += sRed[(fh2 * 4 + w4) * 8 + kf];
            out[b * 16384 + ij * 16 + f] = sv;
        }
    }
}

extern "C" void kernel_launch(void* const* d_in, const int* in_sizes, int n_in,
                              void* d_out, int out_size) {
    const float* in = (const float*)d_in[0];   // inputs (4,32,32,16)
    const float* Mm = (const float*)d_in[1];   // M (32,32,1,32,32,1)
    const float* Ww = (const float*)d_in[2];   // W (32,32,1,32,32,1)
    const float* Gg = (const float*)d_in[3];   // G (32,32,3,3,16,16)
    float* out = (float*)d_out;

    cudaFuncSetAttribute(inrf_kernel,
                         cudaFuncAttributeMaxDynamicSharedMemorySize, SMEM_BYTES);
    inrf_kernel<<<1024, 256, SMEM_BYTES>>>(in, Mm, Ww, Gg, out);
}

// round 15
// speedup vs baseline: 1.3101x; 1.3101x over previous
#include <cuda_runtime.h>

// INRF: out[b,i,j,c] = sum_yx M[ij,yx]*in[b,yx,c]
//                    - L * sum_yx W[ij,yx]*relu(in[b,yx,c] - shifted[b,ij,yx,c])
// shifted[b,ij,y,x,f] = sum_{kh,kw,c} in[b,y+kh-1,x+kw-1,c] * G[ij,kh,kw,c,f]
// B=4, H=W=32, C=F=16, KH=KW=3, L=1, SAME padding.
//
// Persistent-CTA version: grid = 296 (exactly 2 CTAs/SM, one wave). Work
// units are (b,ij) in b-major order; CTA r takes units [r*4096/296,
// (r+1)*4096/296) -> 13-14 units each (3% imbalance). The sIn image tile
// depends only on b, so each CTA fills it ~1.3x total instead of 4x
// (R14's fill was ~32% of issue demand). Fill uses float4 gmem loads.
// Math body = R14's balanced P=8/F=8 f-split packed-FFMA2 loop.

typedef unsigned long long u64;
#define FULLMASK 0xFFFFFFFFu

#define FMA2(d, a, b, c) \
    asm("fma.rn.f32x2 %0, %1, %2, %3;" : "=l"(d) : "l"(a), "l"(b), "l"(c))

__device__ __forceinline__ u64 pk(float x) {
    u64 v = (u64)__float_as_uint(x);
    return v | (v << 32);
}
__device__ __forceinline__ float lo32(u64 v) {
    return __uint_as_float((unsigned)v);
}
__device__ __forceinline__ float hi32(u64 v) {
    return __uint_as_float((unsigned)(v >> 32));
}

// SMEM layout (floats):
//  [0,2304)        G[ij]  : [kh][kw][c][f]
//  [2304,3328)     M row  : 1024
//  [3328,4352)     W row  : 1024
//  [4352,22848)    input tile, channel-major padded: [16][34][34]
//  [22848,23360)   reduction buffer (8 warps x 8 used)
#define OFF_M   2304
#define OFF_W   3328
#define OFF_IN  4352
#define OFF_RED 22848
#define SMEM_FLOATS 23360
#define SMEM_BYTES  (SMEM_FLOATS * 4)

#define NCTA 296
#define NUNITS 4096

__global__ __launch_bounds__(256)
void inrf_kernel(const float* __restrict__ in,   // [4][32][32][16]
                 const float* __restrict__ Mm,   // [1024][1024]
                 const float* __restrict__ Ww,   // [1024][1024]
                 const float* __restrict__ Gg,   // [1024][3][3][16][16]
                 float* __restrict__ out)        // [4][32][32][16]
{
    extern __shared__ float sm[];
    float* sG   = sm;
    float* sM   = sm + OFF_M;
    float* sW   = sm + OFF_W;
    float* sIn  = sm + OFF_IN;
    float* sRed = sm + OFF_RED;

    const int t  = threadIdx.x;      // 0..255
    const int warp = t >> 5, lane = t & 31;
    const int fh = warp >> 2;        // filter half: 0 -> f0-7, 1 -> f8-15
    const int pw = warp & 3;         // position-warp 0..3
    const int fb = fh << 3;          // filter base (0 or 8)
    const int y0 = pw;               // 0..3 ; positions rows 4 apart
    const int x0 = lane;             // 0..31

    const int u_beg = (int)(((long long)blockIdx.x * NUNITS) / NCTA);
    const int u_end = (int)(((long long)(blockIdx.x + 1) * NUNITS) / NCTA);

    int cur_b = -1;

    for (int u = u_beg; u < u_end; u++) {
        const int b  = u >> 10;
        const int ij = u & 1023;

        __syncthreads();   // previous unit fully done (incl. sRed readers)

        // ---- fill image tile when b changes (b-major => rare) ----
        if (b != cur_b) {
            cur_b = b;
            // 1156 (y,x) cells x 4 channel-groups, float4 loads.
            for (int e = t; e < 4624; e += 256) {
                const int yx = e >> 2, cg = e & 3;
                const int y = yx / 34;
                const int x = yx - y * 34;
                float4 v = make_float4(0.f, 0.f, 0.f, 0.f);
                if (y >= 1 && y <= 32 && x >= 1 && x <= 32)
                    v = *reinterpret_cast<const float4*>(
                        in + b * 16384 + (y - 1) * 512 + (x - 1) * 16 + cg * 4);
                const int base = cg * 4624 + yx;   // c = cg*4 + j, c*1156
                sIn[base]        = v.x;
                sIn[base + 1156] = v.y;
                sIn[base + 2312] = v.z;
                sIn[base + 3468] = v.w;
            }
        }

        // ---- per-ij weights ----
        for (int i = t; i < 2304; i += 256) sG[i] = Gg[ij * 2304 + i];
        for (int i = t; i < 1024; i += 256) {
            sM[i] = Mm[ij * 1024 + i];
            sW[i] = Ww[ij * 1024 + i];
        }
        __syncthreads();

        // ---- compute: 8 positions x 4 filter-pairs (this warp's f-half) ----
        u64 s[8][4];
        #pragma unroll
        for (int p = 0; p < 8; p++)
            #pragma unroll
            for (int k = 0; k < 4; k++) s[p][k] = 0ull;

        for (int kk = 0; kk < 9; kk++) {
            const int kh = kk / 3, kw = kk - kh * 3;
            const int o = (y0 + kh) * 34 + (x0 + kw);
            const ulonglong2* gq =
                reinterpret_cast<const ulonglong2*>(sG + (kk << 8) + fb);
            #pragma unroll
            for (int c = 0; c < 16; c++) {
                const float* pc = sIn + c * 1156 + o;
                float a[8];
                #pragma unroll
                for (int p = 0; p < 8; p++) a[p] = pc[p * 136];  // 4 rows apart
                const ulonglong2 q0 = gq[c << 2];     // 16-float stride = 4 u128
                const ulonglong2 q1 = gq[(c << 2) + 1];
                #pragma unroll
                for (int p = 0; p < 8; p++) {
                    const u64 ap = pk(a[p]);
                    FMA2(s[p][0], ap, q0.x, s[p][0]);
                    FMA2(s[p][1], ap, q0.y, s[p][1]);
                    FMA2(s[p][2], ap, q1.x, s[p][2]);
                    FMA2(s[p][3], ap, q1.y, s[p][3]);
                }
            }
        }

        // ---- epilogue: acc8[k] = sum_p m*iv - w*relu(iv - shifted) ----
        float acc8[8];
        #pragma unroll
        for (int k = 0; k < 8; k++) acc8[k] = 0.0f;
        #pragma unroll
        for (int p = 0; p < 8; p++) {
            const int yx = pw * 32 + lane + p * 128;
            const float wv = sW[yx], mv = sM[yx];
            const float* iv = sIn + (y0 + p * 4 + 1) * 34 + (x0 + 1);
            #pragma unroll
            for (int k = 0; k < 4; k++) {
                const float v0 = iv[(fb + 2 * k) * 1156];
                const float v1 = iv[(fb + 2 * k + 1) * 1156];
                acc8[2 * k]     += mv * v0 - wv * fmaxf(v0 - lo32(s[p][k]), 0.0f);
                acc8[2 * k + 1] += mv * v1 - wv * fmaxf(v1 - hi32(s[p][k]), 0.0f);
            }
        }

        // ---- reduce over lanes, then over the 4 position-warps per f-half ----
        #pragma unroll
        for (int k = 0; k < 8; k++) {
            #pragma unroll
            for (int off = 16; off; off >>= 1)
                acc8[k] += __shfl_down_sync(FULLMASK, acc8[k], off);
        }
        if (lane == 0) {
            #pragma unroll
            for (int k = 0; k < 8; k++) sRed[warp * 8 + k] = acc8[k];
        }
        __syncthreads();
        if (t < 16) {
            const int f = t;
            const int fh2 = f >> 3, kf = f & 7;
            float sv = 0.0f;
            #pragma unroll
            for (int w4 = 0; w4 < 4; w4++)
                sv += sRed[(fh2 * 4 + w4) * 8 + kf];
            out[b * 16384 + ij * 16 + f] = sv;
        }
    }
}

extern "C" void kernel_launch(void* const* d_in, const int* in_sizes, int n_in,
                              void* d_out, int out_size) {
    const float* in = (const float*)d_in[0];   // inputs (4,32,32,16)
    const float* Mm = (const float*)d_in[1];   // M (32,32,1,32,32,1)
    const float* Ww = (const float*)d_in[2];   // W (32,32,1,32,32,1)
    const float* Gg = (const float*)d_in[3];   // G (32,32,3,3,16,16)
    float* out = (float*)d_out;

    cudaFuncSetAttribute(inrf_kernel,
                         cudaFuncAttributeMaxDynamicSharedMemorySize, SMEM_BYTES);
    inrf_kernel<<<NCTA, 256, SMEM_BYTES>>>(in, Mm, Ww, Gg, out);
}

// round 16
// speedup vs baseline: 1.4041x; 1.0718x over previous
#include <cuda_runtime.h>

// INRF: out[b,i,j,c] = sum_yx M[ij,yx]*in[b,yx,c]
//                    - L * sum_yx W[ij,yx]*relu(in[b,yx,c] - shifted[b,ij,yx,c])
// shifted[b,ij,y,x,f] = sum_{kh,kw,c} in[b,y+kh-1,x+kw-1,c] * G[ij,kh,kw,c,f]
// B=4, H=W=32, C=F=16, KH=KW=3, L=1, SAME padding.
//
// Persistent CTAs (296, 2/SM, b-major units) as R15. NEW: each thread's 8
// positions are 8 CONSECUTIVE x in one row, so for fixed (c,kh) one 10-float
// row segment covers all 3 kw taps of all 8 positions -> a-loads per (c,kh)
// drop 24 -> 10 wf. Per-c L1 load: 102 wf x 16 warps = 1632 < 2304 fma-cyc
// -> fma-bound (R15 was dead-even 2304/2304).
// Warp layout: warps 0-3 -> filters 0-7, warps 4-7 -> filters 8-15;
// warp w covers rows (w&3)*8 .. +7; lane: row = (w&3)*8+(lane>>2),
// x0 = (lane&3)*8.

typedef unsigned long long u64;
#define FULLMASK 0xFFFFFFFFu

#define FMA2(d, a, b, c) \
    asm("fma.rn.f32x2 %0, %1, %2, %3;" : "=l"(d) : "l"(a), "l"(b), "l"(c))

__device__ __forceinline__ u64 pk(float x) {
    u64 v = (u64)__float_as_uint(x);
    return v | (v << 32);
}
__device__ __forceinline__ float lo32(u64 v) {
    return __uint_as_float((unsigned)v);
}
__device__ __forceinline__ float hi32(u64 v) {
    return __uint_as_float((unsigned)(v >> 32));
}

// SMEM layout (floats):
//  [0,2304)        G[ij]  : [kh][kw][c][f]
//  [2304,3328)     M row  : 1024
//  [3328,4352)     W row  : 1024
//  [4352,22848)    input tile, channel-major padded: [16][34][34]
//  [22848,23360)   reduction buffer (8 warps x 8 used)
#define OFF_M   2304
#define OFF_W   3328
#define OFF_IN  4352
#define OFF_RED 22848
#define SMEM_FLOATS 23360
#define SMEM_BYTES  (SMEM_FLOATS * 4)

#define NCTA 296
#define NUNITS 4096

__global__ __launch_bounds__(256)
void inrf_kernel(const float* __restrict__ in,   // [4][32][32][16]
                 const float* __restrict__ Mm,   // [1024][1024]
                 const float* __restrict__ Ww,   // [1024][1024]
                 const float* __restrict__ Gg,   // [1024][3][3][16][16]
                 float* __restrict__ out)        // [4][32][32][16]
{
    extern __shared__ float sm[];
    float* sG   = sm;
    float* sM   = sm + OFF_M;
    float* sW   = sm + OFF_W;
    float* sIn  = sm + OFF_IN;
    float* sRed = sm + OFF_RED;

    const int t  = threadIdx.x;      // 0..255
    const int warp = t >> 5, lane = t & 31;
    const int fh = warp >> 2;        // filter half: 0 -> f0-7, 1 -> f8-15
    const int fb = fh << 3;          // filter base (0 or 8)
    const int y  = (warp & 3) * 8 + (lane >> 2);   // row 0..31
    const int x0 = (lane & 3) * 8;                 // 0,8,16,24

    const int u_beg = (int)(((long long)blockIdx.x * NUNITS) / NCTA);
    const int u_end = (int)(((long long)(blockIdx.x + 1) * NUNITS) / NCTA);

    int cur_b = -1;

    for (int u = u_beg; u < u_end; u++) {
        const int b  = u >> 10;
        const int ij = u & 1023;

        __syncthreads();   // previous unit fully done (incl. sRed readers)

        // ---- fill image tile when b changes (b-major => rare) ----
        if (b != cur_b) {
            cur_b = b;
            for (int e = t; e < 4624; e += 256) {
                const int yx = e >> 2, cg = e & 3;
                const int yy = yx / 34;
                const int xx = yx - yy * 34;
                float4 v = make_float4(0.f, 0.f, 0.f, 0.f);
                if (yy >= 1 && yy <= 32 && xx >= 1 && xx <= 32)
                    v = *reinterpret_cast<const float4*>(
                        in + b * 16384 + (yy - 1) * 512 + (xx - 1) * 16 + cg * 4);
                const int base = cg * 4624 + yx;
                sIn[base]        = v.x;
                sIn[base + 1156] = v.y;
                sIn[base + 2312] = v.z;
                sIn[base + 3468] = v.w;
            }
        }

        // ---- per-ij weights ----
        for (int i = t; i < 2304; i += 256) sG[i] = Gg[ij * 2304 + i];
        for (int i = t; i < 1024; i += 256) {
            sM[i] = Mm[ij * 1024 + i];
            sW[i] = Ww[ij * 1024 + i];
        }
        __syncthreads();

        // ---- compute: 8 consecutive-x positions x 4 filter-pairs ----
        u64 s[8][4];
        #pragma unroll
        for (int p = 0; p < 8; p++)
            #pragma unroll
            for (int k = 0; k < 4; k++) s[p][k] = 0ull;

        for (int c = 0; c < 16; c++) {
            const float* cbase = sIn + c * 1156 + x0;
            #pragma unroll
            for (int kh = 0; kh < 3; kh++) {
                const float* pr = cbase + (y + kh) * 34;
                // 10-float row segment covers kw 0..2 for positions x0..x0+7
                float r[10];
                #pragma unroll
                for (int j = 0; j < 10; j++) r[j] = pr[j];
                // g for the 3 kw taps of this kh, this f-half (8 floats each)
                const float* gk = sG + ((kh * 3) << 8) + (c << 4) + fb;
                const ulonglong2 qa0 = *reinterpret_cast<const ulonglong2*>(gk);
                const ulonglong2 qa1 = *reinterpret_cast<const ulonglong2*>(gk + 4);
                const ulonglong2 qb0 = *reinterpret_cast<const ulonglong2*>(gk + 256);
                const ulonglong2 qb1 = *reinterpret_cast<const ulonglong2*>(gk + 260);
                const ulonglong2 qc0 = *reinterpret_cast<const ulonglong2*>(gk + 512);
                const ulonglong2 qc1 = *reinterpret_cast<const ulonglong2*>(gk + 516);
                #pragma unroll
                for (int p = 0; p < 8; p++) {
                    const u64 a0 = pk(r[p]);
                    FMA2(s[p][0], a0, qa0.x, s[p][0]);
                    FMA2(s[p][1], a0, qa0.y, s[p][1]);
                    FMA2(s[p][2], a0, qa1.x, s[p][2]);
                    FMA2(s[p][3], a0, qa1.y, s[p][3]);
                    const u64 a1 = pk(r[p + 1]);
                    FMA2(s[p][0], a1, qb0.x, s[p][0]);
                    FMA2(s[p][1], a1, qb0.y, s[p][1]);
                    FMA2(s[p][2], a1, qb1.x, s[p][2]);
                    FMA2(s[p][3], a1, qb1.y, s[p][3]);
                    const u64 a2 = pk(r[p + 2]);
                    FMA2(s[p][0], a2, qc0.x, s[p][0]);
                    FMA2(s[p][1], a2, qc0.y, s[p][1]);
                    FMA2(s[p][2], a2, qc1.x, s[p][2]);
                    FMA2(s[p][3], a2, qc1.y, s[p][3]);
                }
            }
        }

        // ---- epilogue: acc8[k] = sum_p m*iv - w*relu(iv - shifted) ----
        float acc8[8];
        #pragma unroll
        for (int k = 0; k < 8; k++) acc8[k] = 0.0f;
        #pragma unroll
        for (int p = 0; p < 8; p++) {
            const int yx = y * 32 + x0 + p;
            const float wv = sW[yx], mv = sM[yx];
            const float* iv = sIn + (y + 1) * 34 + (x0 + p + 1);
            #pragma unroll
            for (int k = 0; k < 4; k++) {
                const float v0 = iv[(fb + 2 * k) * 1156];
                const float v1 = iv[(fb + 2 * k + 1) * 1156];
                acc8[2 * k]     += mv * v0 - wv * fmaxf(v0 - lo32(s[p][k]), 0.0f);
                acc8[2 * k + 1] += mv * v1 - wv * fmaxf(v1 - hi32(s[p][k]), 0.0f);
            }
        }

        // ---- reduce over lanes, then over the 4 row-warps per f-half ----
        #pragma unroll
        for (int k = 0; k < 8; k++) {
            #pragma unroll
            for (int off = 16; off; off >>= 1)
                acc8[k] += __shfl_down_sync(FULLMASK, acc8[k], off);
        }
        if (lane == 0) {
            #pragma unroll
            for (int k = 0; k < 8; k++) sRed[warp * 8 + k] = acc8[k];
        }
        __syncthreads();
        if (t < 16) {
            const int f = t;
            const int fh2 = f >> 3, kf = f & 7;
            float sv = 0.0f;
            #pragma unroll
            for (int w4 = 0; w4 < 4; w4++)
                sv += sRed[(fh2 * 4 + w4) * 8 + kf];
            out[b * 16384 + ij * 16 + f] = sv;
        }
    }
}

extern "C" void kernel_launch(void* const* d_in, const int* in_sizes, int n_in,
                              void* d_out, int out_size) {
    const float* in = (const float*)d_in[0];   // inputs (4,32,32,16)
    const float* Mm = (const float*)d_in[1];   // M (32,32,1,32,32,1)
    const float* Ww = (const float*)d_in[2];   // W (32,32,1,32,32,1)
    const float* Gg = (const float*)d_in[3];   // G (32,32,3,3,16,16)
    float* out = (float*)d_out;

    cudaFuncSetAttribute(inrf_kernel,
                         cudaFuncAttributeMaxDynamicSharedMemorySize, SMEM_BYTES);
    inrf_kernel<<<NCTA, 256, SMEM_BYTES>>>(in, Mm, Ww, Gg, out);
}